// round 4
// baseline (speedup 1.0000x reference)
#include <cuda_runtime.h>
#include <cuda_bf16.h>
#include <math.h>

// Problem constants
#define N_    1024
#define L_    128
#define WD_   300
#define PD_   50
#define D_    400          // WD + 2*PD
#define FS_   3
#define NF_   512
#define C_    53
#define LP_   126          // L - FS + 1
#define KTOT  1200         // FS * D
#define NEG_  (-1e30f)

// Scratch (device globals: no allocs allowed)
__device__ float g_X[(size_t)N_ * L_ * D_];        // 200 MB embedded input
__device__ float g_feat[(size_t)N_ * 3 * NF_];     // 6 MB pooled features, layout [n][f*3+seg]

// ---------------------------------------------------------------------------
// Kernel 1: embedding gather.  One block per (n,l) position, 128 threads.
// dst row = [wordvec[token] (300) | pf1_emb[p1] (50) | pf2_emb[p2] (50)]
// ---------------------------------------------------------------------------
__global__ __launch_bounds__(128) void gather_kernel(
    const int* __restrict__ tokens, const int* __restrict__ pf1,
    const int* __restrict__ pf2,
    const float* __restrict__ wordvec, const float* __restrict__ pf1_emb,
    const float* __restrict__ pf2_emb)
{
    int id = blockIdx.x;                       // 0 .. N*L-1
    float* dst = g_X + (size_t)id * D_;
    int t = threadIdx.x;
    if (t < 75) {
        // 300 floats = 75 float4 (1200B rows, 16B aligned)
        const float4* src = reinterpret_cast<const float4*>(wordvec + (size_t)tokens[id] * WD_);
        reinterpret_cast<float4*>(dst)[t] = src[t];
    } else if (t < 100) {
        int j = t - 75;                        // 50 floats = 25 float2
        const float2* src = reinterpret_cast<const float2*>(pf1_emb + pf1[id] * PD_);
        reinterpret_cast<float2*>(dst + WD_)[j] = src[j];
    } else if (t < 125) {
        int j = t - 100;
        const float2* src = reinterpret_cast<const float2*>(pf2_emb + pf2[id] * PD_);
        reinterpret_cast<float2*>(dst + WD_ + PD_)[j] = src[j];
    }
}

// ---------------------------------------------------------------------------
// Kernel 2: conv GEMM + tanh + piecewise max pooling.
// Key identity: im2col[t][kk] = Xflat[t*400 + kk], kk in [0,1200)  (overlap rows)
// Grid: (NF/64, N).  Block 256 threads = 16x16, each computes 8(M) x 4(N).
// ---------------------------------------------------------------------------
#define BM 128
#define BN 64
#define BK 16
#define ASTR (BM + 4)   // 132
#define BSTR (BN + 4)   // 68

__global__ __launch_bounds__(256) void conv_pool_kernel(
    const float* __restrict__ conv_w, const float* __restrict__ conv_b,
    const int* __restrict__ entity_pos)
{
    __shared__ float As[BK][ASTR];
    __shared__ float Bs[BK][BSTR];
    __shared__ float red[16][3 * BN];

    const int n  = blockIdx.y;
    const int f0 = blockIdx.x * BN;
    const float* Xn = g_X + (size_t)n * (L_ * D_);

    const int tid = threadIdx.x;
    const int ry = tid >> 4;          // 0..15 -> rows ry*8 .. ry*8+7
    const int rx = tid & 15;          // 0..15 -> cols rx*4 .. rx*4+3

    float acc[8][4];
#pragma unroll
    for (int i = 0; i < 8; i++)
#pragma unroll
        for (int j = 0; j < 4; j++) acc[i][j] = 0.f;

    for (int k0 = 0; k0 < KTOT; k0 += BK) {
        // --- load A tile: 128 rows x 16 k = 512 float4, 2 per thread ---
#pragma unroll
        for (int i = 0; i < 2; i++) {
            int idx = tid + i * 256;           // 0..511
            int t   = idx >> 2;                // row 0..127
            int c4  = idx & 3;                 // which float4 of the 16-wide chunk
            float4 v;
            if (t < LP_)                       // rows >=126 are pad; also avoids OOB at n=1023
                v = *reinterpret_cast<const float4*>(Xn + t * D_ + k0 + c4 * 4);
            else
                v = make_float4(0.f, 0.f, 0.f, 0.f);
            int kk = c4 * 4;
            As[kk + 0][t] = v.x; As[kk + 1][t] = v.y;
            As[kk + 2][t] = v.z; As[kk + 3][t] = v.w;
        }
        // --- load B tile: 64 f x 16 k = 256 float4, 1 per thread ---
        {
            int f  = tid >> 2;
            int c4 = tid & 3;
            float4 v = *reinterpret_cast<const float4*>(
                conv_w + (size_t)(f0 + f) * KTOT + k0 + c4 * 4);
            int kk = c4 * 4;
            Bs[kk + 0][f] = v.x; Bs[kk + 1][f] = v.y;
            Bs[kk + 2][f] = v.z; Bs[kk + 3][f] = v.w;
        }
        __syncthreads();

#pragma unroll
        for (int kk = 0; kk < BK; kk++) {
            float4 a0 = *reinterpret_cast<const float4*>(&As[kk][ry * 8]);
            float4 a1 = *reinterpret_cast<const float4*>(&As[kk][ry * 8 + 4]);
            float4 bv = *reinterpret_cast<const float4*>(&Bs[kk][rx * 4]);
            float a[8] = {a0.x, a0.y, a0.z, a0.w, a1.x, a1.y, a1.z, a1.w};
            float b[4] = {bv.x, bv.y, bv.z, bv.w};
#pragma unroll
            for (int i = 0; i < 8; i++)
#pragma unroll
                for (int j = 0; j < 4; j++) acc[i][j] += a[i] * b[j];
        }
        __syncthreads();
    }

    // --- epilogue: bias + tanh + 3-segment masked max over t ---
    const int p1 = entity_pos[2 * n];
    const int p2 = entity_pos[2 * n + 1];
    float bias[4];
#pragma unroll
    for (int j = 0; j < 4; j++) bias[j] = conv_b[f0 + rx * 4 + j];

    float m[3][4];
#pragma unroll
    for (int s = 0; s < 3; s++)
#pragma unroll
        for (int j = 0; j < 4; j++) m[s][j] = NEG_;

#pragma unroll
    for (int i = 0; i < 8; i++) {
        int t = ry * 8 + i;
        if (t < LP_) {
            bool in1 = (t <= p1);
            bool in2 = (t >= p1) && (t <= p2);
            bool in3 = (t >= p2);
#pragma unroll
            for (int j = 0; j < 4; j++) {
                float v = tanhf(acc[i][j] + bias[j]);
                if (in1) m[0][j] = fmaxf(m[0][j], v);
                if (in2) m[1][j] = fmaxf(m[1][j], v);
                if (in3) m[2][j] = fmaxf(m[2][j], v);
            }
        }
    }

#pragma unroll
    for (int s = 0; s < 3; s++)
#pragma unroll
        for (int j = 0; j < 4; j++) red[ry][s * BN + rx * 4 + j] = m[s][j];
    __syncthreads();

    if (tid < 3 * BN) {
        float mm = NEG_;
#pragma unroll
        for (int r = 0; r < 16; r++) mm = fmaxf(mm, red[r][tid]);
        int seg = tid >> 6;          // tid / 64
        int fc  = tid & 63;
        // feat layout from reference: feat[n, f*3 + seg]
        g_feat[(size_t)n * (3 * NF_) + (size_t)(f0 + fc) * 3 + seg] = mm;
    }
}

// ---------------------------------------------------------------------------
// Kernel 3: out[n][c] = feat[n] @ out_w + out_b.  One block per sentence.
// 256 threads = 4 j-groups x 64 c-lanes.
// ---------------------------------------------------------------------------
__global__ __launch_bounds__(256) void out_gemm_kernel(
    const float* __restrict__ out_w, const float* __restrict__ out_b,
    float* __restrict__ out)
{
    __shared__ float sf[3 * NF_];
    __shared__ float part[4][64];
    const int n = blockIdx.x;

    for (int i = threadIdx.x; i < 3 * NF_; i += 256)
        sf[i] = g_feat[(size_t)n * (3 * NF_) + i];
    __syncthreads();

    const int g = threadIdx.x >> 6;      // 0..3
    const int c = threadIdx.x & 63;
    float a = 0.f;
    if (c < C_) {
        const int j0 = g * (3 * NF_ / 4);
#pragma unroll 4
        for (int j = j0; j < j0 + (3 * NF_ / 4); j++)
            a += sf[j] * out_w[j * C_ + c];
    }
    part[g][c] = a;
    __syncthreads();

    if (threadIdx.x < C_) {
        float s = part[0][threadIdx.x] + part[1][threadIdx.x] +
                  part[2][threadIdx.x] + part[3][threadIdx.x] + out_b[threadIdx.x];
        out[(size_t)n * C_ + threadIdx.x] = s;
    }
}

// ---------------------------------------------------------------------------
// Launch.  Input order (metadata): tokens, pf1, pf2, entity_pos, wordvec,
// pf1_emb, pf2_emb, conv_w, conv_b, out_w, out_b.  Output: float32 [N, C].
// ---------------------------------------------------------------------------
extern "C" void kernel_launch(void* const* d_in, const int* in_sizes, int n_in,
                              void* d_out, int out_size)
{
    const int*   tokens     = (const int*)d_in[0];
    const int*   pf1        = (const int*)d_in[1];
    const int*   pf2        = (const int*)d_in[2];
    const int*   entity_pos = (const int*)d_in[3];
    const float* wordvec    = (const float*)d_in[4];
    const float* pf1_emb    = (const float*)d_in[5];
    const float* pf2_emb    = (const float*)d_in[6];
    const float* conv_w     = (const float*)d_in[7];
    const float* conv_b     = (const float*)d_in[8];
    const float* out_w      = (const float*)d_in[9];
    const float* out_b      = (const float*)d_in[10];
    float* out = (float*)d_out;

    gather_kernel<<<N_ * L_, 128>>>(tokens, pf1, pf2, wordvec, pf1_emb, pf2_emb);
    conv_pool_kernel<<<dim3(NF_ / BN, N_), 256>>>(conv_w, conv_b, entity_pos);
    out_gemm_kernel<<<N_, 256>>>(out_w, out_b, out);
}

// round 8
// speedup vs baseline: 2.1890x; 2.1890x over previous
#include <cuda_runtime.h>
#include <cuda_bf16.h>
#include <cstdint>
#include <math.h>

// Problem constants
#define N_    1024
#define L_    128
#define WD_   300
#define PD_   50
#define D_    400          // WD + 2*PD
#define FS_   3
#define NF_   512
#define C_    53
#define LP_   126          // L - FS + 1
#define KTOT  1200         // FS * D
#define KPAD  1216         // padded to 19*64
#define KC    64
#define NKC   19
#define NEG_  (-1e30f)

// ---------------------------------------------------------------------------
// Scratch (device globals; no allocs allowed)
// ---------------------------------------------------------------------------
__device__ __align__(256) __nv_bfloat16 g_Xhi[(size_t)N_ * L_ * D_ + 2048];
__device__ __align__(256) __nv_bfloat16 g_Xlo[(size_t)N_ * L_ * D_ + 2048];
__device__ __align__(256) __nv_bfloat16 g_Whi[NF_ * KPAD];
__device__ __align__(256) __nv_bfloat16 g_Wlo[NF_ * KPAD];
__device__ float g_feat[(size_t)N_ * 3 * NF_];   // [n][f*3+seg]

// ---------------------------------------------------------------------------
// Helpers (baseline ISA only: cp.async / ldmatrix / mma.sync)
// ---------------------------------------------------------------------------
__device__ __forceinline__ uint32_t smem_u32(const void* p) {
    uint32_t a;
    asm("{ .reg .u64 t; cvta.to.shared.u64 t, %1; cvt.u32.u64 %0, t; }" : "=r"(a) : "l"(p));
    return a;
}
#define CP_ASYNC16(dst, src) \
    asm volatile("cp.async.cg.shared.global [%0], [%1], 16;" :: "r"(dst), "l"(src) : "memory")
#define CP_COMMIT()  asm volatile("cp.async.commit_group;" ::: "memory")
#define CP_WAIT1()   asm volatile("cp.async.wait_group 1;" ::: "memory")
#define CP_WAIT0()   asm volatile("cp.async.wait_group 0;" ::: "memory")

#define LDSM_X4(d0, d1, d2, d3, addr) \
    asm volatile("ldmatrix.sync.aligned.m8n8.x4.shared.b16 {%0,%1,%2,%3}, [%4];" \
                 : "=r"(d0), "=r"(d1), "=r"(d2), "=r"(d3) : "r"(addr))

#define MMA16816(cc, a0, a1, a2, a3, b0, b1) \
    asm volatile("mma.sync.aligned.m16n8k16.row.col.f32.bf16.bf16.f32 " \
                 "{%0,%1,%2,%3}, {%4,%5,%6,%7}, {%8,%9}, {%0,%1,%2,%3};" \
                 : "+f"((cc)[0]), "+f"((cc)[1]), "+f"((cc)[2]), "+f"((cc)[3]) \
                 : "r"(a0), "r"(a1), "r"(a2), "r"(a3), "r"(b0), "r"(b1))

__device__ __forceinline__ void split2(float v, __nv_bfloat16& h, __nv_bfloat16& l) {
    h = __float2bfloat16(v);
    l = __float2bfloat16(v - __bfloat162float(h));
}

// ---------------------------------------------------------------------------
// Kernel 1: embedding gather -> split bf16 hi/lo
// ---------------------------------------------------------------------------
__global__ __launch_bounds__(128) void gather2_kernel(
    const int* __restrict__ tokens, const int* __restrict__ pf1,
    const int* __restrict__ pf2,
    const float* __restrict__ wordvec, const float* __restrict__ pf1_emb,
    const float* __restrict__ pf2_emb)
{
    int id = blockIdx.x;                     // (n,l)
    size_t base = (size_t)id * D_;
    int t = threadIdx.x;
    if (t < 75) {
        float4 v = reinterpret_cast<const float4*>(wordvec + (size_t)tokens[id] * WD_)[t];
        __nv_bfloat16 h[4], l[4];
        split2(v.x, h[0], l[0]); split2(v.y, h[1], l[1]);
        split2(v.z, h[2], l[2]); split2(v.w, h[3], l[3]);
        *reinterpret_cast<uint2*>(&g_Xhi[base + t * 4]) = *reinterpret_cast<uint2*>(h);
        *reinterpret_cast<uint2*>(&g_Xlo[base + t * 4]) = *reinterpret_cast<uint2*>(l);
    } else if (t < 100) {
        int j = t - 75;
        float2 v = reinterpret_cast<const float2*>(pf1_emb + pf1[id] * PD_)[j];
        __nv_bfloat16 h[2], l[2];
        split2(v.x, h[0], l[0]); split2(v.y, h[1], l[1]);
        *reinterpret_cast<uint32_t*>(&g_Xhi[base + WD_ + j * 2]) = *reinterpret_cast<uint32_t*>(h);
        *reinterpret_cast<uint32_t*>(&g_Xlo[base + WD_ + j * 2]) = *reinterpret_cast<uint32_t*>(l);
    } else if (t < 125) {
        int j = t - 100;
        float2 v = reinterpret_cast<const float2*>(pf2_emb + pf2[id] * PD_)[j];
        __nv_bfloat16 h[2], l[2];
        split2(v.x, h[0], l[0]); split2(v.y, h[1], l[1]);
        *reinterpret_cast<uint32_t*>(&g_Xhi[base + WD_ + PD_ + j * 2]) = *reinterpret_cast<uint32_t*>(h);
        *reinterpret_cast<uint32_t*>(&g_Xlo[base + WD_ + PD_ + j * 2]) = *reinterpret_cast<uint32_t*>(l);
    }
}

// ---------------------------------------------------------------------------
// Kernel 1b: split conv_w into bf16 hi/lo, zero-padded K 1200->1216
// ---------------------------------------------------------------------------
__global__ __launch_bounds__(256) void wsplit_kernel(const float* __restrict__ conv_w)
{
    int idx = blockIdx.x * 256 + threadIdx.x;      // 0 .. NF_*KPAD-1
    int f = idx / KPAD, k = idx % KPAD;
    float v = (k < KTOT) ? conv_w[(size_t)f * KTOT + k] : 0.f;
    __nv_bfloat16 h, l;
    split2(v, h, l);
    g_Whi[idx] = h;
    g_Wlo[idx] = l;
}

// ---------------------------------------------------------------------------
// Kernel 2: mma.sync (HMMA bf16) conv GEMM, 3-term split + tanh + pool.
// Grid (2, N_): blockIdx.x = N-half (256 filters), blockIdx.y = sentence.
// 8 warps = 2(M) x 4(N); warp tile 64x64; CTA tile 128x256.
// Stage (per k-chunk of 64): Ahi 16K | Alo 16K | Bhi 32K | Blo 32K = 96KB, x2.
// ---------------------------------------------------------------------------
#define STAGE_SZ 98304
#define A_LO_OFF 16384
#define B_HI_OFF 32768
#define B_LO_OFF 65536
#define SM_BIAS  196608
#define SM_DYN   197632
#define RED_STR  264

struct LoadCtx { size_t xbase; int nh; };

__device__ __forceinline__ void load_stage(uint32_t sbase, int tid,
                                           const LoadCtx& lc, int k0)
{
#pragma unroll
    for (int i = 0; i < 4; i++) {          // A: 128 rows x 8 chunks, hi+lo
        int idx = tid + i * 256;
        int r = idx >> 3, c = idx & 7;
        uint32_t d = sbase + r * 128 + ((uint32_t)(c ^ (r & 7)) << 4);
        const size_t xo = lc.xbase + (size_t)r * D_ + k0 + c * 8;
        CP_ASYNC16(d, g_Xhi + xo);
        CP_ASYNC16(d + A_LO_OFF, g_Xlo + xo);
    }
#pragma unroll
    for (int i = 0; i < 8; i++) {          // B: 256 rows x 8 chunks, hi+lo
        int idx = tid + i * 256;
        int r = idx >> 3, c = idx & 7;
        uint32_t d = sbase + B_HI_OFF + r * 128 + ((uint32_t)(c ^ (r & 7)) << 4);
        const size_t wo = (size_t)(lc.nh * 256 + r) * KPAD + k0 + c * 8;
        CP_ASYNC16(d, g_Whi + wo);
        CP_ASYNC16(d + 32768, g_Wlo + wo);
    }
}

__global__ __launch_bounds__(256, 1) void conv_hmma_kernel(
    const float* __restrict__ conv_b, const int* __restrict__ entity_pos)
{
    extern __shared__ char smem[];
    const uint32_t sb = smem_u32(smem);
    const int tid  = threadIdx.x;
    const int lane = tid & 31, wid = tid >> 5;
    const int wm = wid & 1, wn = wid >> 1;       // warp grid 2(M) x 4(N)
    const int nh = blockIdx.x;                    // filter half
    const int n  = blockIdx.y;                    // sentence

    float* biasS = reinterpret_cast<float*>(smem + SM_BIAS);
    biasS[tid] = conv_b[nh * 256 + tid];

    LoadCtx lc;
    lc.xbase = (size_t)n * (L_ * D_);
    lc.nh = nh;

    // ldmatrix lane addressing (x4, plain — B is [n][k] K-major = col-major kxn)
    // A tiles order: (m-lo,k-lo)(m-hi,k-lo)(m-lo,k-hi)(m-hi,k-hi) -> a0..a3
    const int rowA = wm * 64 + ((lane >> 3) & 1) * 8 + (lane & 7);
    const int haA  = lane >> 4;                   // k-half select
    const uint32_t offA = rowA * 128;
    const int saA = rowA & 7;
    // B tiles order: (n-lo,k-lo)(n-lo,k-hi)(n-hi,k-lo)(n-hi,k-hi) -> d0..d3
    const int rowB = wn * 64 + ((lane >> 4) & 1) * 8 + (lane & 7);
    const int hbB  = (lane >> 3) & 1;             // k-half select
    const uint32_t offB = rowB * 128;
    const int sbB = rowB & 7;

    float acc[4][8][4];                           // [m16 i][n8 q][4]
#pragma unroll
    for (int i = 0; i < 4; i++)
#pragma unroll
        for (int q = 0; q < 8; q++)
#pragma unroll
            for (int v = 0; v < 4; v++) acc[i][q][v] = 0.f;

    load_stage(sb, tid, lc, 0);
    CP_COMMIT();

    for (int kc = 0; kc < NKC; kc++) {
        if (kc + 1 < NKC) {
            load_stage(sb + ((kc + 1) & 1) * STAGE_SZ, tid, lc, (kc + 1) * KC);
            CP_COMMIT();
            CP_WAIT1();
        } else {
            CP_WAIT0();
        }
        __syncthreads();

        const uint32_t stg = sb + (kc & 1) * STAGE_SZ;
#pragma unroll
        for (int pass = 0; pass < 3; pass++) {
            // pass0: Ahi*Bhi  pass1: Ahi*Blo  pass2: Alo*Bhi
            const uint32_t aBase = stg + (pass == 2 ? A_LO_OFF : 0);
            const uint32_t bBase = stg + (pass == 1 ? B_LO_OFF : B_HI_OFF);
#pragma unroll
            for (int ks = 0; ks < 4; ks++) {
                uint32_t a[4][4];
#pragma unroll
                for (int i = 0; i < 4; i++) {
                    uint32_t ad = aBase + offA + i * 2048
                                + ((uint32_t)((ks * 2 + haA) ^ saA) << 4);
                    LDSM_X4(a[i][0], a[i][1], a[i][2], a[i][3], ad);
                }
#pragma unroll
                for (int j = 0; j < 4; j++) {
                    uint32_t b0, b1, b2, b3;
                    uint32_t bd = bBase + offB + j * 2048
                                + ((uint32_t)((ks * 2 + hbB) ^ sbB) << 4);
                    LDSM_X4(b0, b1, b2, b3, bd);
#pragma unroll
                    for (int i = 0; i < 4; i++) {
                        MMA16816(acc[i][j * 2],     a[i][0], a[i][1], a[i][2], a[i][3], b0, b1);
                        MMA16816(acc[i][j * 2 + 1], a[i][0], a[i][1], a[i][2], a[i][3], b2, b3);
                    }
                }
            }
        }
        __syncthreads();
    }

    // ---- epilogue: bias + tanh -> smem, then 3-segment max over t ----
    float* red = reinterpret_cast<float*>(smem);        // [128][RED_STR]
    const int r0b = wm * 64 + (lane >> 2);
    const int c0b = wn * 64 + (lane & 3) * 2;
#pragma unroll
    for (int i = 0; i < 4; i++) {
#pragma unroll
        for (int q = 0; q < 8; q++) {
            const int r0 = r0b + i * 16;
            const int c0 = c0b + q * 8;
            red[r0 * RED_STR + c0]           = tanhf(acc[i][q][0] + biasS[c0]);
            red[r0 * RED_STR + c0 + 1]       = tanhf(acc[i][q][1] + biasS[c0 + 1]);
            red[(r0 + 8) * RED_STR + c0]     = tanhf(acc[i][q][2] + biasS[c0]);
            red[(r0 + 8) * RED_STR + c0 + 1] = tanhf(acc[i][q][3] + biasS[c0 + 1]);
        }
    }
    __syncthreads();

    const int p1 = entity_pos[2 * n];
    const int p2 = entity_pos[2 * n + 1];
    const int c = tid;                                   // 0..255
    float m0 = NEG_, m1 = NEG_, m2 = NEG_;
    for (int t = 0; t < LP_; t++) {
        float v = red[t * RED_STR + c];
        if (t <= p1) m0 = fmaxf(m0, v);
        if (t >= p1 && t <= p2) m1 = fmaxf(m1, v);
        if (t >= p2) m2 = fmaxf(m2, v);
    }
    const size_t fo = (size_t)n * (3 * NF_) + (size_t)(nh * 256 + c) * 3;
    g_feat[fo + 0] = m0;
    g_feat[fo + 1] = m1;
    g_feat[fo + 2] = m2;
}

// ---------------------------------------------------------------------------
// Kernel 3: out[n][c] = feat[n] @ out_w + out_b
// ---------------------------------------------------------------------------
__global__ __launch_bounds__(256) void out_gemm_kernel(
    const float* __restrict__ out_w, const float* __restrict__ out_b,
    float* __restrict__ out)
{
    __shared__ float sf[3 * NF_];
    __shared__ float part[4][64];
    const int n = blockIdx.x;

    for (int i = threadIdx.x; i < 3 * NF_; i += 256)
        sf[i] = g_feat[(size_t)n * (3 * NF_) + i];
    __syncthreads();

    const int g = threadIdx.x >> 6;
    const int c = threadIdx.x & 63;
    float a = 0.f;
    if (c < C_) {
        const int j0 = g * (3 * NF_ / 4);
#pragma unroll 4
        for (int j = j0; j < j0 + (3 * NF_ / 4); j++)
            a += sf[j] * out_w[j * C_ + c];
    }
    part[g][c] = a;
    __syncthreads();

    if (threadIdx.x < C_) {
        float s = part[0][threadIdx.x] + part[1][threadIdx.x] +
                  part[2][threadIdx.x] + part[3][threadIdx.x] + out_b[threadIdx.x];
        out[(size_t)n * C_ + threadIdx.x] = s;
    }
}

// ---------------------------------------------------------------------------
// Launch. Inputs: tokens, pf1, pf2, entity_pos, wordvec, pf1_emb, pf2_emb,
// conv_w, conv_b, out_w, out_b.  Output: float32 [N, C].
// ---------------------------------------------------------------------------
extern "C" void kernel_launch(void* const* d_in, const int* in_sizes, int n_in,
                              void* d_out, int out_size)
{
    const int*   tokens     = (const int*)d_in[0];
    const int*   pf1        = (const int*)d_in[1];
    const int*   pf2        = (const int*)d_in[2];
    const int*   entity_pos = (const int*)d_in[3];
    const float* wordvec    = (const float*)d_in[4];
    const float* pf1_emb    = (const float*)d_in[5];
    const float* pf2_emb    = (const float*)d_in[6];
    const float* conv_w     = (const float*)d_in[7];
    const float* conv_b     = (const float*)d_in[8];
    const float* out_w      = (const float*)d_in[9];
    const float* out_b      = (const float*)d_in[10];
    float* out = (float*)d_out;

    cudaFuncSetAttribute(conv_hmma_kernel,
                         cudaFuncAttributeMaxDynamicSharedMemorySize, SM_DYN);

    gather2_kernel<<<N_ * L_, 128>>>(tokens, pf1, pf2, wordvec, pf1_emb, pf2_emb);
    wsplit_kernel<<<(NF_ * KPAD) / 256, 256>>>(conv_w);
    conv_hmma_kernel<<<dim3(2, N_), 256, SM_DYN>>>(conv_b, entity_pos);
    out_gemm_kernel<<<N_, 256>>>(out_w, out_b, out);
}

// round 9
// speedup vs baseline: 4.0322x; 1.8420x over previous
#include <cuda_runtime.h>
#include <cuda_fp16.h>
#include <cstdint>
#include <math.h>

// Problem constants
#define N_    1024
#define L_    128
#define WD_   300
#define PD_   50
#define D_    400          // WD + 2*PD
#define FS_   3
#define NF_   512
#define C_    53
#define LP_   126          // L - FS + 1
#define KTOT  1200         // FS * D
#define KPAD  1216         // padded to 19*64
#define KC    64
#define NKC   19
#define NEG_  (-1e30f)

// ---------------------------------------------------------------------------
// Scratch (device globals; no allocs allowed)
// ---------------------------------------------------------------------------
__device__ __align__(256) __half g_X[(size_t)N_ * L_ * D_ + 2048];   // fp16 rounded X
__device__ __align__(256) __half g_Whi[NF_ * KPAD];
__device__ __align__(256) __half g_Wlo[NF_ * KPAD];
__device__ float g_feat[(size_t)N_ * 3 * NF_];   // [n][f*3+seg]

// ---------------------------------------------------------------------------
// Helpers (baseline ISA only: cp.async / ldmatrix / mma.sync)
// ---------------------------------------------------------------------------
__device__ __forceinline__ uint32_t smem_u32(const void* p) {
    uint32_t a;
    asm("{ .reg .u64 t; cvta.to.shared.u64 t, %1; cvt.u32.u64 %0, t; }" : "=r"(a) : "l"(p));
    return a;
}
#define CP_ASYNC16(dst, src) \
    asm volatile("cp.async.cg.shared.global [%0], [%1], 16;" :: "r"(dst), "l"(src) : "memory")
#define CP_COMMIT()  asm volatile("cp.async.commit_group;" ::: "memory")
#define CP_WAIT1()   asm volatile("cp.async.wait_group 1;" ::: "memory")
#define CP_WAIT0()   asm volatile("cp.async.wait_group 0;" ::: "memory")

#define LDSM_X4(d0, d1, d2, d3, addr) \
    asm volatile("ldmatrix.sync.aligned.m8n8.x4.shared.b16 {%0,%1,%2,%3}, [%4];" \
                 : "=r"(d0), "=r"(d1), "=r"(d2), "=r"(d3) : "r"(addr))

#define MMAF16(cc, a0, a1, a2, a3, b0, b1) \
    asm volatile("mma.sync.aligned.m16n8k16.row.col.f32.f16.f16.f32 " \
                 "{%0,%1,%2,%3}, {%4,%5,%6,%7}, {%8,%9}, {%0,%1,%2,%3};" \
                 : "+f"((cc)[0]), "+f"((cc)[1]), "+f"((cc)[2]), "+f"((cc)[3]) \
                 : "r"(a0), "r"(a1), "r"(a2), "r"(a3), "r"(b0), "r"(b1))

// ---------------------------------------------------------------------------
// Kernel 1: embedding gather -> fp16 (rounded, no split)
// ---------------------------------------------------------------------------
__global__ __launch_bounds__(128) void gather_kernel(
    const int* __restrict__ tokens, const int* __restrict__ pf1,
    const int* __restrict__ pf2,
    const float* __restrict__ wordvec, const float* __restrict__ pf1_emb,
    const float* __restrict__ pf2_emb)
{
    int id = blockIdx.x;                     // (n,l)
    size_t base = (size_t)id * D_;
    int t = threadIdx.x;
    if (t < 75) {
        float4 v = reinterpret_cast<const float4*>(wordvec + (size_t)tokens[id] * WD_)[t];
        __half h[4] = {__float2half(v.x), __float2half(v.y),
                       __float2half(v.z), __float2half(v.w)};
        *reinterpret_cast<uint2*>(&g_X[base + t * 4]) = *reinterpret_cast<uint2*>(h);
    } else if (t < 100) {
        int j = t - 75;
        float2 v = reinterpret_cast<const float2*>(pf1_emb + pf1[id] * PD_)[j];
        __half h[2] = {__float2half(v.x), __float2half(v.y)};
        *reinterpret_cast<uint32_t*>(&g_X[base + WD_ + j * 2]) = *reinterpret_cast<uint32_t*>(h);
    } else if (t < 125) {
        int j = t - 100;
        float2 v = reinterpret_cast<const float2*>(pf2_emb + pf2[id] * PD_)[j];
        __half h[2] = {__float2half(v.x), __float2half(v.y)};
        *reinterpret_cast<uint32_t*>(&g_X[base + WD_ + PD_ + j * 2]) = *reinterpret_cast<uint32_t*>(h);
    }
}

// ---------------------------------------------------------------------------
// Kernel 1b: split conv_w into fp16 hi/lo, zero-padded K 1200->1216
// ---------------------------------------------------------------------------
__global__ __launch_bounds__(256) void wsplit_kernel(const float* __restrict__ conv_w)
{
    int idx = blockIdx.x * 256 + threadIdx.x;      // 0 .. NF_*KPAD-1
    int f = idx / KPAD, k = idx % KPAD;
    float v = (k < KTOT) ? conv_w[(size_t)f * KTOT + k] : 0.f;
    __half h = __float2half(v);
    __half l = __float2half(v - __half2float(h));
    g_Whi[idx] = h;
    g_Wlo[idx] = l;
}

// ---------------------------------------------------------------------------
// Kernel 2: mma.sync fp16 conv GEMM, 2-product W-split + tanh + pool.
// Grid (4, N_): blockIdx.x = filter quarter (128 f), blockIdx.y = sentence.
// 8 warps = 4(M) x 2(N); warp tile 32x64; CTA tile 128x128. 2 CTAs/SM.
// Stage: A 16K | Bhi 16K | Blo 16K = 48KB, x2 buffered.
// ---------------------------------------------------------------------------
#define STAGE_SZ 49152
#define BH_OFF   16384
#define BL_OFF   32768
#define SM_BIAS  98304
#define SM_DYN   98816
#define RED_STR  132

struct LoadCtx { size_t xbase; int nb; };

__device__ __forceinline__ void load_stage(uint32_t sbase, int tid,
                                           const LoadCtx& lc, int k0)
{
#pragma unroll
    for (int i = 0; i < 4; i++) {          // A: 128 rows x 8 chunks of 16B
        int idx = tid + i * 256;
        int r = idx >> 3, c = idx & 7;
        uint32_t d = sbase + r * 128 + ((uint32_t)(c ^ (r & 7)) << 4);
        CP_ASYNC16(d, g_X + lc.xbase + (size_t)r * D_ + k0 + c * 8);
    }
#pragma unroll
    for (int i = 0; i < 4; i++) {          // Bhi + Blo: 128 rows x 8 chunks
        int idx = tid + i * 256;
        int r = idx >> 3, c = idx & 7;
        uint32_t d = sbase + BH_OFF + r * 128 + ((uint32_t)(c ^ (r & 7)) << 4);
        const size_t wo = (size_t)(lc.nb * 128 + r) * KPAD + k0 + c * 8;
        CP_ASYNC16(d, g_Whi + wo);
        CP_ASYNC16(d + 16384, g_Wlo + wo);
    }
}

__global__ __launch_bounds__(256, 2) void conv_hmma_kernel(
    const float* __restrict__ conv_b, const int* __restrict__ entity_pos)
{
    extern __shared__ char smem[];
    const uint32_t sb = smem_u32(smem);
    const int tid  = threadIdx.x;
    const int lane = tid & 31, wid = tid >> 5;
    const int wm = wid & 3, wn = wid >> 2;       // warp grid 4(M) x 2(N)
    const int nb = blockIdx.x;                    // filter quarter
    const int n  = blockIdx.y;                    // sentence

    float* biasS = reinterpret_cast<float*>(smem + SM_BIAS);
    if (tid < 128) biasS[tid] = conv_b[nb * 128 + tid];

    LoadCtx lc;
    lc.xbase = (size_t)n * (L_ * D_);
    lc.nb = nb;

    // ldmatrix lane addressing (identical formulas to the verified R6 kernel,
    // warp-tile rebased: A rows wm*32 + i*16, B rows wn*64 + j*16)
    const int rowA = wm * 32 + ((lane >> 3) & 1) * 8 + (lane & 7);
    const int haA  = lane >> 4;
    const uint32_t offA = rowA * 128;
    const int saA = rowA & 7;
    const int rowB = wn * 64 + ((lane >> 4) & 1) * 8 + (lane & 7);
    const int hbB  = (lane >> 3) & 1;
    const uint32_t offB = rowB * 128;
    const int sbB = rowB & 7;

    float acc[2][8][4];                           // [m16 i][n8 q][4]
#pragma unroll
    for (int i = 0; i < 2; i++)
#pragma unroll
        for (int q = 0; q < 8; q++)
#pragma unroll
            for (int v = 0; v < 4; v++) acc[i][q][v] = 0.f;

    load_stage(sb, tid, lc, 0);
    CP_COMMIT();

    for (int kc = 0; kc < NKC; kc++) {
        if (kc + 1 < NKC) {
            load_stage(sb + ((kc + 1) & 1) * STAGE_SZ, tid, lc, (kc + 1) * KC);
            CP_COMMIT();
            CP_WAIT1();
        } else {
            CP_WAIT0();
        }
        __syncthreads();

        const uint32_t stg = sb + (kc & 1) * STAGE_SZ;
#pragma unroll
        for (int ks = 0; ks < 4; ks++) {
            uint32_t a[2][4];
#pragma unroll
            for (int i = 0; i < 2; i++) {
                uint32_t ad = stg + offA + i * 2048
                            + ((uint32_t)((ks * 2 + haA) ^ saA) << 4);
                LDSM_X4(a[i][0], a[i][1], a[i][2], a[i][3], ad);
            }
#pragma unroll
            for (int j = 0; j < 4; j++) {
                const uint32_t brel = offB + j * 2048
                                    + ((uint32_t)((ks * 2 + hbB) ^ sbB) << 4);
                uint32_t h0, h1, h2, h3, l0, l1, l2, l3;
                LDSM_X4(h0, h1, h2, h3, stg + BH_OFF + brel);
                LDSM_X4(l0, l1, l2, l3, stg + BL_OFF + brel);
#pragma unroll
                for (int i = 0; i < 2; i++) {
                    MMAF16(acc[i][j * 2],     a[i][0], a[i][1], a[i][2], a[i][3], h0, h1);
                    MMAF16(acc[i][j * 2 + 1], a[i][0], a[i][1], a[i][2], a[i][3], h2, h3);
                    MMAF16(acc[i][j * 2],     a[i][0], a[i][1], a[i][2], a[i][3], l0, l1);
                    MMAF16(acc[i][j * 2 + 1], a[i][0], a[i][1], a[i][2], a[i][3], l2, l3);
                }
            }
        }
        __syncthreads();
    }

    // ---- epilogue: bias + tanh -> smem, then 3-segment max over t ----
    float* red = reinterpret_cast<float*>(smem);        // [128][RED_STR]
    const int r0b = wm * 32 + (lane >> 2);
    const int c0b = wn * 64 + (lane & 3) * 2;
#pragma unroll
    for (int i = 0; i < 2; i++) {
#pragma unroll
        for (int q = 0; q < 8; q++) {
            const int r0 = r0b + i * 16;
            const int c0 = c0b + q * 8;
            red[r0 * RED_STR + c0]           = tanhf(acc[i][q][0] + biasS[c0]);
            red[r0 * RED_STR + c0 + 1]       = tanhf(acc[i][q][1] + biasS[c0 + 1]);
            red[(r0 + 8) * RED_STR + c0]     = tanhf(acc[i][q][2] + biasS[c0]);
            red[(r0 + 8) * RED_STR + c0 + 1] = tanhf(acc[i][q][3] + biasS[c0 + 1]);
        }
    }
    __syncthreads();

    const int p1 = entity_pos[2 * n];
    const int p2 = entity_pos[2 * n + 1];
    float* part = red + 128 * RED_STR;                   // [2][3][128]
    {
        const int half = tid >> 7, c = tid & 127;
        const int t0 = half ? 64 : 0;
        const int t1 = half ? (LP_ - 1) : 63;
        float m0 = NEG_, m1 = NEG_, m2 = NEG_;
        for (int t = t0; t <= t1; t++) {
            float v = red[t * RED_STR + c];
            if (t <= p1) m0 = fmaxf(m0, v);
            if (t >= p1 && t <= p2) m1 = fmaxf(m1, v);
            if (t >= p2) m2 = fmaxf(m2, v);
        }
        part[(half * 3 + 0) * 128 + c] = m0;
        part[(half * 3 + 1) * 128 + c] = m1;
        part[(half * 3 + 2) * 128 + c] = m2;
    }
    __syncthreads();

    if (tid < 128) {
        const size_t fo = (size_t)n * (3 * NF_) + (size_t)(nb * 128 + tid) * 3;
#pragma unroll
        for (int s = 0; s < 3; s++)
            g_feat[fo + s] = fmaxf(part[s * 128 + tid], part[(3 + s) * 128 + tid]);
    }
}

// ---------------------------------------------------------------------------
// Kernel 3: out[n][c] = feat[n] @ out_w + out_b
// ---------------------------------------------------------------------------
__global__ __launch_bounds__(256) void out_gemm_kernel(
    const float* __restrict__ out_w, const float* __restrict__ out_b,
    float* __restrict__ out)
{
    __shared__ float sf[3 * NF_];
    __shared__ float part[4][64];
    const int n = blockIdx.x;

    for (int i = threadIdx.x; i < 3 * NF_; i += 256)
        sf[i] = g_feat[(size_t)n * (3 * NF_) + i];
    __syncthreads();

    const int g = threadIdx.x >> 6;
    const int c = threadIdx.x & 63;
    float a = 0.f;
    if (c < C_) {
        const int j0 = g * (3 * NF_ / 4);
#pragma unroll 4
        for (int j = j0; j < j0 + (3 * NF_ / 4); j++)
            a += sf[j] * out_w[j * C_ + c];
    }
    part[g][c] = a;
    __syncthreads();

    if (threadIdx.x < C_) {
        float s = part[0][threadIdx.x] + part[1][threadIdx.x] +
                  part[2][threadIdx.x] + part[3][threadIdx.x] + out_b[threadIdx.x];
        out[(size_t)n * C_ + threadIdx.x] = s;
    }
}

// ---------------------------------------------------------------------------
// Launch. Inputs: tokens, pf1, pf2, entity_pos, wordvec, pf1_emb, pf2_emb,
// conv_w, conv_b, out_w, out_b.  Output: float32 [N, C].
// ---------------------------------------------------------------------------
extern "C" void kernel_launch(void* const* d_in, const int* in_sizes, int n_in,
                              void* d_out, int out_size)
{
    const int*   tokens     = (const int*)d_in[0];
    const int*   pf1        = (const int*)d_in[1];
    const int*   pf2        = (const int*)d_in[2];
    const int*   entity_pos = (const int*)d_in[3];
    const float* wordvec    = (const float*)d_in[4];
    const float* pf1_emb    = (const float*)d_in[5];
    const float* pf2_emb    = (const float*)d_in[6];
    const float* conv_w     = (const float*)d_in[7];
    const float* conv_b     = (const float*)d_in[8];
    const float* out_w      = (const float*)d_in[9];
    const float* out_b      = (const float*)d_in[10];
    float* out = (float*)d_out;

    cudaFuncSetAttribute(conv_hmma_kernel,
                         cudaFuncAttributeMaxDynamicSharedMemorySize, SM_DYN);

    gather_kernel<<<N_ * L_, 128>>>(tokens, pf1, pf2, wordvec, pf1_emb, pf2_emb);
    wsplit_kernel<<<(NF_ * KPAD) / 256, 256>>>(conv_w);
    conv_hmma_kernel<<<dim3(4, N_), 256, SM_DYN>>>(conv_b, entity_pos);
    out_gemm_kernel<<<N_, 256>>>(out_w, out_b, out);
}

// round 11
// speedup vs baseline: 5.9883x; 1.4851x over previous
#include <cuda_runtime.h>
#include <cuda_fp16.h>
#include <cstdint>
#include <math.h>

// Problem constants
#define N_    1024
#define L_    128
#define WD_   300
#define PD_   50
#define D_    400          // WD + 2*PD
#define FS_   3
#define NF_   512
#define C_    53
#define LP_   126          // L - FS + 1
#define KTOT  1200         // FS * D
#define KPAD  1216         // padded to 19*64
#define KC    64
#define NKC   19
#define NEG_  (-1e30f)

// ---------------------------------------------------------------------------
// Scratch (device globals; no allocs allowed)
// ---------------------------------------------------------------------------
__device__ __align__(256) __half g_X[(size_t)N_ * L_ * D_ + 2048];   // fp16 X
__device__ __align__(256) __half g_W[NF_ * KPAD];                    // fp16 W
__device__ float g_feat[(size_t)N_ * 3 * NF_];   // [n][f*3+seg]

// ---------------------------------------------------------------------------
// Helpers (baseline ISA only: cp.async / ldmatrix / mma.sync)
// ---------------------------------------------------------------------------
__device__ __forceinline__ uint32_t smem_u32(const void* p) {
    uint32_t a;
    asm("{ .reg .u64 t; cvta.to.shared.u64 t, %1; cvt.u32.u64 %0, t; }" : "=r"(a) : "l"(p));
    return a;
}
#define CP_ASYNC16(dst, src) \
    asm volatile("cp.async.cg.shared.global [%0], [%1], 16;" :: "r"(dst), "l"(src) : "memory")
#define CP_COMMIT()  asm volatile("cp.async.commit_group;" ::: "memory")
#define CP_WAIT1()   asm volatile("cp.async.wait_group 1;" ::: "memory")
#define CP_WAIT0()   asm volatile("cp.async.wait_group 0;" ::: "memory")

#define LDSM_X4(d0, d1, d2, d3, addr) \
    asm volatile("ldmatrix.sync.aligned.m8n8.x4.shared.b16 {%0,%1,%2,%3}, [%4];" \
                 : "=r"(d0), "=r"(d1), "=r"(d2), "=r"(d3) : "r"(addr))

#define MMAF16(cc, a0, a1, a2, a3, b0, b1) \
    asm volatile("mma.sync.aligned.m16n8k16.row.col.f32.f16.f16.f32 " \
                 "{%0,%1,%2,%3}, {%4,%5,%6,%7}, {%8,%9}, {%0,%1,%2,%3};" \
                 : "+f"((cc)[0]), "+f"((cc)[1]), "+f"((cc)[2]), "+f"((cc)[3]) \
                 : "r"(a0), "r"(a1), "r"(a2), "r"(a3), "r"(b0), "r"(b1))

// ---------------------------------------------------------------------------
// Kernel 1: embedding gather -> fp16
// ---------------------------------------------------------------------------
__global__ __launch_bounds__(128) void gather_kernel(
    const int* __restrict__ tokens, const int* __restrict__ pf1,
    const int* __restrict__ pf2,
    const float* __restrict__ wordvec, const float* __restrict__ pf1_emb,
    const float* __restrict__ pf2_emb)
{
    int id = blockIdx.x;                     // (n,l)
    size_t base = (size_t)id * D_;
    int t = threadIdx.x;
    if (t < 75) {
        float4 v = reinterpret_cast<const float4*>(wordvec + (size_t)tokens[id] * WD_)[t];
        __half h[4] = {__float2half(v.x), __float2half(v.y),
                       __float2half(v.z), __float2half(v.w)};
        *reinterpret_cast<uint2*>(&g_X[base + t * 4]) = *reinterpret_cast<uint2*>(h);
    } else if (t < 100) {
        int j = t - 75;
        float2 v = reinterpret_cast<const float2*>(pf1_emb + pf1[id] * PD_)[j];
        __half h[2] = {__float2half(v.x), __float2half(v.y)};
        *reinterpret_cast<uint32_t*>(&g_X[base + WD_ + j * 2]) = *reinterpret_cast<uint32_t*>(h);
    } else if (t < 125) {
        int j = t - 100;
        float2 v = reinterpret_cast<const float2*>(pf2_emb + pf2[id] * PD_)[j];
        __half h[2] = {__float2half(v.x), __float2half(v.y)};
        *reinterpret_cast<uint32_t*>(&g_X[base + WD_ + PD_ + j * 2]) = *reinterpret_cast<uint32_t*>(h);
    }
}

// ---------------------------------------------------------------------------
// Kernel 1b: convert conv_w to fp16, zero-padded K 1200->1216
// ---------------------------------------------------------------------------
__global__ __launch_bounds__(256) void wconv_kernel(const float* __restrict__ conv_w)
{
    int idx = blockIdx.x * 256 + threadIdx.x;      // 0 .. NF_*KPAD-1
    int f = idx / KPAD, k = idx % KPAD;
    float v = (k < KTOT) ? conv_w[(size_t)f * KTOT + k] : 0.f;
    g_W[idx] = __float2half(v);
}

// ---------------------------------------------------------------------------
// Kernel 2: mma.sync fp16 conv GEMM (single product) + tanh + pool.
// Grid (4, N_): blockIdx.x = filter quarter (128 f), blockIdx.y = sentence.
// 8 warps = 4(M) x 2(N); warp tile 32x64; CTA tile 128x128. 2 CTAs/SM.
// Stage: A 16K | B 16K = 32KB, x2 buffered.
// ---------------------------------------------------------------------------
#define STAGE_SZ 32768
#define B_OFF    16384
#define SM_BIAS  70656      // beyond stages (65536) and epilogue red+part (70656)
#define SM_DYN   71168
#define RED_STR  132

struct LoadCtx { size_t xbase; int nb; };

__device__ __forceinline__ void load_stage(uint32_t sbase, int tid,
                                           const LoadCtx& lc, int k0)
{
#pragma unroll
    for (int i = 0; i < 4; i++) {          // A: 128 rows x 8 chunks of 16B
        int idx = tid + i * 256;
        int r = idx >> 3, c = idx & 7;
        uint32_t d = sbase + r * 128 + ((uint32_t)(c ^ (r & 7)) << 4);
        CP_ASYNC16(d, g_X + lc.xbase + (size_t)r * D_ + k0 + c * 8);
    }
#pragma unroll
    for (int i = 0; i < 4; i++) {          // B: 128 rows x 8 chunks of 16B
        int idx = tid + i * 256;
        int r = idx >> 3, c = idx & 7;
        uint32_t d = sbase + B_OFF + r * 128 + ((uint32_t)(c ^ (r & 7)) << 4);
        CP_ASYNC16(d, g_W + (size_t)(lc.nb * 128 + r) * KPAD + k0 + c * 8);
    }
}

__global__ __launch_bounds__(256, 2) void conv_hmma_kernel(
    const float* __restrict__ conv_b, const int* __restrict__ entity_pos)
{
    extern __shared__ char smem[];
    const uint32_t sb = smem_u32(smem);
    const int tid  = threadIdx.x;
    const int lane = tid & 31, wid = tid >> 5;
    const int wm = wid & 3, wn = wid >> 2;       // warp grid 4(M) x 2(N)
    const int nb = blockIdx.x;                    // filter quarter
    const int n  = blockIdx.y;                    // sentence

    float* biasS = reinterpret_cast<float*>(smem + SM_BIAS);
    if (tid < 128) biasS[tid] = conv_b[nb * 128 + tid];

    LoadCtx lc;
    lc.xbase = (size_t)n * (L_ * D_);
    lc.nb = nb;

    // ldmatrix lane addressing (verified fragment maps, warp-tile rebased)
    const int rowA = wm * 32 + ((lane >> 3) & 1) * 8 + (lane & 7);
    const int haA  = lane >> 4;
    const uint32_t offA = rowA * 128;
    const int saA = rowA & 7;
    const int rowB = wn * 64 + ((lane >> 4) & 1) * 8 + (lane & 7);
    const int hbB  = (lane >> 3) & 1;
    const uint32_t offB = rowB * 128;
    const int sbB = rowB & 7;

    float acc[2][8][4];                           // [m16 i][n8 q][4]
#pragma unroll
    for (int i = 0; i < 2; i++)
#pragma unroll
        for (int q = 0; q < 8; q++)
#pragma unroll
            for (int v = 0; v < 4; v++) acc[i][q][v] = 0.f;

    load_stage(sb, tid, lc, 0);
    CP_COMMIT();

    for (int kc = 0; kc < NKC; kc++) {
        if (kc + 1 < NKC) {
            load_stage(sb + ((kc + 1) & 1) * STAGE_SZ, tid, lc, (kc + 1) * KC);
            CP_COMMIT();
            CP_WAIT1();
        } else {
            CP_WAIT0();
        }
        __syncthreads();

        const uint32_t stg = sb + (kc & 1) * STAGE_SZ;
#pragma unroll
        for (int ks = 0; ks < 4; ks++) {
            uint32_t a[2][4];
#pragma unroll
            for (int i = 0; i < 2; i++) {
                uint32_t ad = stg + offA + i * 2048
                            + ((uint32_t)((ks * 2 + haA) ^ saA) << 4);
                LDSM_X4(a[i][0], a[i][1], a[i][2], a[i][3], ad);
            }
#pragma unroll
            for (int j = 0; j < 4; j++) {
                uint32_t b0, b1, b2, b3;
                uint32_t bd = stg + B_OFF + offB + j * 2048
                            + ((uint32_t)((ks * 2 + hbB) ^ sbB) << 4);
                LDSM_X4(b0, b1, b2, b3, bd);
#pragma unroll
                for (int i = 0; i < 2; i++) {
                    MMAF16(acc[i][j * 2],     a[i][0], a[i][1], a[i][2], a[i][3], b0, b1);
                    MMAF16(acc[i][j * 2 + 1], a[i][0], a[i][1], a[i][2], a[i][3], b2, b3);
                }
            }
        }
        __syncthreads();
    }

    // ---- epilogue: bias + tanh -> smem, then 3-segment max over t ----
    float* red = reinterpret_cast<float*>(smem);        // [128][RED_STR]
    const int r0b = wm * 32 + (lane >> 2);
    const int c0b = wn * 64 + (lane & 3) * 2;
#pragma unroll
    for (int i = 0; i < 2; i++) {
#pragma unroll
        for (int q = 0; q < 8; q++) {
            const int r0 = r0b + i * 16;
            const int c0 = c0b + q * 8;
            red[r0 * RED_STR + c0]           = tanhf(acc[i][q][0] + biasS[c0]);
            red[r0 * RED_STR + c0 + 1]       = tanhf(acc[i][q][1] + biasS[c0 + 1]);
            red[(r0 + 8) * RED_STR + c0]     = tanhf(acc[i][q][2] + biasS[c0]);
            red[(r0 + 8) * RED_STR + c0 + 1] = tanhf(acc[i][q][3] + biasS[c0 + 1]);
        }
    }
    __syncthreads();

    const int p1 = entity_pos[2 * n];
    const int p2 = entity_pos[2 * n + 1];
    float* part = red + 128 * RED_STR;                   // [2][3][128]
    {
        const int half = tid >> 7, c = tid & 127;
        const int t0 = half ? 64 : 0;
        const int t1 = half ? (LP_ - 1) : 63;
        float m0 = NEG_, m1 = NEG_, m2 = NEG_;
        for (int t = t0; t <= t1; t++) {
            float v = red[t * RED_STR + c];
            if (t <= p1) m0 = fmaxf(m0, v);
            if (t >= p1 && t <= p2) m1 = fmaxf(m1, v);
            if (t >= p2) m2 = fmaxf(m2, v);
        }
        part[(half * 3 + 0) * 128 + c] = m0;
        part[(half * 3 + 1) * 128 + c] = m1;
        part[(half * 3 + 2) * 128 + c] = m2;
    }
    __syncthreads();

    if (tid < 128) {
        const size_t fo = (size_t)n * (3 * NF_) + (size_t)(nb * 128 + tid) * 3;
#pragma unroll
        for (int s = 0; s < 3; s++)
            g_feat[fo + s] = fmaxf(part[s * 128 + tid], part[(3 + s) * 128 + tid]);
    }
}

// ---------------------------------------------------------------------------
// Kernel 3: out[n][c] = feat[n] @ out_w + out_b
// ---------------------------------------------------------------------------
__global__ __launch_bounds__(256) void out_gemm_kernel(
    const float* __restrict__ out_w, const float* __restrict__ out_b,
    float* __restrict__ out)
{
    __shared__ float sf[3 * NF_];
    __shared__ float part[4][64];
    const int n = blockIdx.x;

    for (int i = threadIdx.x; i < 3 * NF_; i += 256)
        sf[i] = g_feat[(size_t)n * (3 * NF_) + i];
    __syncthreads();

    const int g = threadIdx.x >> 6;
    const int c = threadIdx.x & 63;
    float a = 0.f;
    if (c < C_) {
        const int j0 = g * (3 * NF_ / 4);
#pragma unroll 4
        for (int j = j0; j < j0 + (3 * NF_ / 4); j++)
            a += sf[j] * out_w[j * C_ + c];
    }
    part[g][c] = a;
    __syncthreads();

    if (threadIdx.x < C_) {
        float s = part[0][threadIdx.x] + part[1][threadIdx.x] +
                  part[2][threadIdx.x] + part[3][threadIdx.x] + out_b[threadIdx.x];
        out[(size_t)n * C_ + threadIdx.x] = s;
    }
}

// ---------------------------------------------------------------------------
// Launch. Inputs: tokens, pf1, pf2, entity_pos, wordvec, pf1_emb, pf2_emb,
// conv_w, conv_b, out_w, out_b.  Output: float32 [N, C].
// ---------------------------------------------------------------------------
extern "C" void kernel_launch(void* const* d_in, const int* in_sizes, int n_in,
                              void* d_out, int out_size)
{
    const int*   tokens     = (const int*)d_in[0];
    const int*   pf1        = (const int*)d_in[1];
    const int*   pf2        = (const int*)d_in[2];
    const int*   entity_pos = (const int*)d_in[3];
    const float* wordvec    = (const float*)d_in[4];
    const float* pf1_emb    = (const float*)d_in[5];
    const float* pf2_emb    = (const float*)d_in[6];
    const float* conv_w     = (const float*)d_in[7];
    const float* conv_b     = (const float*)d_in[8];
    const float* out_w      = (const float*)d_in[9];
    const float* out_b      = (const float*)d_in[10];
    float* out = (float*)d_out;

    cudaFuncSetAttribute(conv_hmma_kernel,
                         cudaFuncAttributeMaxDynamicSharedMemorySize, SM_DYN);

    gather_kernel<<<N_ * L_, 128>>>(tokens, pf1, pf2, wordvec, pf1_emb, pf2_emb);
    wconv_kernel<<<(NF_ * KPAD) / 256, 256>>>(conv_w);
    conv_hmma_kernel<<<dim3(4, N_), 256, SM_DYN>>>(conv_b, entity_pos);
    out_gemm_kernel<<<N_, 256>>>(out_w, out_b, out);
}